// round 4
// baseline (speedup 1.0000x reference)
#include <cuda_runtime.h>
#include <cstdint>

// Sparse 3D conv via mma.sync tf32 (sm_80+ portable tensor path; tcgen05 PTX is
// rejected because the harness targets compute_103 without the 'a' suffix).
// out[out_map[k,m]] += feats[in_map[k,m]] @ kernel[k]
// N=200000, K=27, M=50000, Cin=Cout=64, fp32 in/out, tf32(RNA) MMA.

#define KOFF    27
#define MPAIRS  50000
#define NVOX    200000
#define CIN     64
#define COUT    64
#define TILE_M  128
#define NTHREADS 128
#define FSTRIDE 68            // A tile stride: 64 + 4 pad, conflict-free LDS
#define SMEM_WORDS (TILE_M * FSTRIDE + CIN * COUT)   // A tile + fragment-packed B

__device__ __forceinline__ uint32_t f2tf32(float f) {
    uint32_t r;
    asm("cvt.rna.tf32.f32 %0, %1;" : "=r"(r) : "f"(f));
    return r;
}

__device__ __forceinline__ void mma_tf32(float c[4], const uint32_t a[4], const uint32_t b[2]) {
    asm volatile(
        "mma.sync.aligned.m16n8k8.row.col.f32.tf32.tf32.f32 "
        "{%0,%1,%2,%3}, {%4,%5,%6,%7}, {%8,%9}, {%0,%1,%2,%3};"
        : "+f"(c[0]), "+f"(c[1]), "+f"(c[2]), "+f"(c[3])
        : "r"(a[0]), "r"(a[1]), "r"(a[2]), "r"(a[3]), "r"(b[0]), "r"(b[1]));
}

__global__ void spconv_zero_kernel(float4* __restrict__ out, int n4) {
    int i = blockIdx.x * blockDim.x + threadIdx.x;
    if (i < n4) out[i] = make_float4(0.f, 0.f, 0.f, 0.f);
}

__global__ __launch_bounds__(NTHREADS, 4)
void spconv_mma_kernel(const float* __restrict__ feats,
                       const float* __restrict__ kern,
                       const int*   __restrict__ in_map,
                       const int*   __restrict__ out_map,
                       float*       __restrict__ out)
{
    extern __shared__ uint32_t sh[];
    uint32_t* Ash   = sh;                       // [TILE_M][FSTRIDE] tf32
    uint32_t* Bpack = sh + TILE_M * FSTRIDE;    // fragment-packed W^T (4096 words)

    const int k   = blockIdx.y;
    const int m0  = blockIdx.x * TILE_M;
    const int tid = threadIdx.x;
    const int wid = tid >> 5;
    const int lid = tid & 31;

    // ---- Gather A: 128 rows x 64 cols, tf32-rounded, STS.128 ----
    {
        const int rlane = tid & 15;            // 16B chunk of the row
        const int rgrp  = tid >> 4;            // 8 rows per sweep
        const int* im = in_map + (size_t)k * MPAIRS;
        #pragma unroll
        for (int r = rgrp; r < TILE_M; r += 8) {
            int m = m0 + r;
            uint4 u = make_uint4(0u, 0u, 0u, 0u);
            if (m < MPAIRS) {
                int row = im[m];
                float4 v = *reinterpret_cast<const float4*>(feats + (size_t)row * CIN + rlane * 4);
                u.x = f2tf32(v.x); u.y = f2tf32(v.y); u.z = f2tf32(v.z); u.w = f2tf32(v.w);
            }
            *reinterpret_cast<uint4*>(Ash + r * FSTRIDE + rlane * 4) = u;
        }
    }

    // ---- Stage B = W[k]^T, fragment-packed, cout rows permuted ----
    // cout perm (for contiguous-cout scatter): P=o>>4, local=o&15, tt=local>>2,
    //   rr=local&3: pos = (2P + (rr>>1))*8 + 2*tt + (rr&1); nt=pos>>3, g=pos&7.
    // fragment packing: cin i -> (s=i>>3, j=i&7, t=j&3, e=j>>2);
    //   Bpack[((nt*8+s)*32 + g*4 + t)*2 + e]  => lane (g*4+t) reads b-pair as LDS.64.
    {
        const float* W = kern + (size_t)k * CIN * COUT;
        #pragma unroll
        for (int idx = tid; idx < CIN * COUT; idx += NTHREADS) {
            int i = idx >> 6;                  // cin
            int o = idx & 63;                  // cout (contiguous -> coalesced LDG)
            int P = o >> 4, local = o & 15;
            int tt = local >> 2, rr = local & 3;
            int pos = (2 * P + (rr >> 1)) * 8 + 2 * tt + (rr & 1);
            int nt = pos >> 3, g = pos & 7;
            int s = i >> 3, j = i & 7;
            int t = j & 3, e = j >> 2;
            Bpack[(((nt * 8 + s) * 32) + g * 4 + t) * 2 + e] = f2tf32(W[idx]);
        }
    }
    __syncthreads();

    // ---- Warp GEMM: rows [32*wid, 32*wid+32), all 64 couts ----
    const int g = lid >> 2;                    // row-group within mma tile
    const int t = lid & 3;                     // thread in group

    float acc[2][8][4];
    #pragma unroll
    for (int mt = 0; mt < 2; ++mt)
        #pragma unroll
        for (int nt = 0; nt < 8; ++nt)
            #pragma unroll
            for (int e = 0; e < 4; ++e) acc[mt][nt][e] = 0.f;

    const int mbase = wid * 32;
    #pragma unroll
    for (int s = 0; s < 8; ++s) {
        const int kc = s * 8;
        uint32_t bf[8][2];
        #pragma unroll
        for (int nt = 0; nt < 8; ++nt) {
            const uint32_t* bp = Bpack + ((nt * 8 + s) * 32 + lid) * 2;
            asm volatile("ld.shared.v2.b32 {%0, %1}, [%2];"
                         : "=r"(bf[nt][0]), "=r"(bf[nt][1]) : "r"((uint32_t)(__cvta_generic_to_shared(bp))));
        }
        uint32_t af[2][4];
        #pragma unroll
        for (int mt = 0; mt < 2; ++mt) {
            const uint32_t* ap = Ash + (mbase + mt * 16 + g) * FSTRIDE + kc + t;
            af[mt][0] = ap[0];
            af[mt][1] = ap[8 * FSTRIDE];
            af[mt][2] = ap[4];
            af[mt][3] = ap[8 * FSTRIDE + 4];
        }
        #pragma unroll
        for (int mt = 0; mt < 2; ++mt)
            #pragma unroll
            for (int nt = 0; nt < 8; ++nt)
                mma_tf32(acc[mt][nt], af[mt], bf[nt]);
    }

    // ---- Scatter: vectorized global reductions, 4 contiguous couts per red ----
    {
        const int* om = out_map + (size_t)k * MPAIRS;
        #pragma unroll
        for (int mt = 0; mt < 2; ++mt) {
            #pragma unroll
            for (int half = 0; half < 2; ++half) {   // rows g and g+8
                int m = m0 + mbase + mt * 16 + g + half * 8;
                if (m < MPAIRS) {
                    int orow = om[m];
                    float* dst = out + (size_t)orow * COUT + t * 4;
                    #pragma unroll
                    for (int P = 0; P < 4; ++P) {
                        // couts 16P + 4t .. +3
                        asm volatile("red.global.add.v4.f32 [%0], {%1,%2,%3,%4};"
                                     :: "l"(dst + 16 * P),
                                        "f"(acc[mt][2 * P][half * 2]),
                                        "f"(acc[mt][2 * P][half * 2 + 1]),
                                        "f"(acc[mt][2 * P + 1][half * 2]),
                                        "f"(acc[mt][2 * P + 1][half * 2 + 1]) : "memory");
                    }
                }
            }
        }
    }
}

extern "C" void kernel_launch(void* const* d_in, const int* in_sizes, int n_in,
                              void* d_out, int out_size) {
    const float* feats   = (const float*)d_in[0];   // [N, 64]
    const float* kern    = (const float*)d_in[1];   // [27, 64, 64]
    const int*   in_map  = (const int*)d_in[2];     // [27, 50000]
    const int*   out_map = (const int*)d_in[3];     // [27, 50000]
    float* out = (float*)d_out;                     // [N, 64]

    int n4 = NVOX * COUT / 4;
    spconv_zero_kernel<<<(n4 + 255) / 256, 256>>>((float4*)out, n4);

    int smem_bytes = SMEM_WORDS * (int)sizeof(uint32_t);   // 51,200 B -> 4 CTAs/SM
    cudaFuncSetAttribute(spconv_mma_kernel,
                         cudaFuncAttributeMaxDynamicSharedMemorySize, smem_bytes);
    dim3 grid((MPAIRS + TILE_M - 1) / TILE_M, KOFF);
    spconv_mma_kernel<<<grid, NTHREADS, smem_bytes>>>(feats, kern, in_map, out_map, out);
}

// round 5
// speedup vs baseline: 1.6090x; 1.6090x over previous
#include <cuda_runtime.h>
#include <cstdint>

// Sparse 3D conv via mma.sync tf32 (sm_80+ portable path; tcgen05 PTX rejected
// by the harness's compute_103 target).
// out[out_map[k,m]] += feats[in_map[k,m]] @ kernel[k]
// N=200000, K=27, M=50000, Cin=Cout=64, fp32 in/out, tf32(RNA) MMA.
//
// R5 config: 512 threads (16 warps), warp tile 32 rows x 32 couts, acc=32 regs
// -> 64-reg cap -> 2 CTAs/SM -> 32 warps/SM (2x R3/R4).

#define KOFF    27
#define MPAIRS  50000
#define NVOX    200000
#define CIN     64
#define COUT    64
#define TILE_M  256
#define NTHREADS 512
#define FSTRIDE 68            // A tile stride: 64 + 4 pad, conflict-free LDS
#define SMEM_WORDS (TILE_M * FSTRIDE + CIN * COUT)   // A tile + fragment-packed B

__device__ __forceinline__ uint32_t f2tf32(float f) {
    uint32_t r;
    asm("cvt.rna.tf32.f32 %0, %1;" : "=r"(r) : "f"(f));
    return r;
}

__device__ __forceinline__ void mma_tf32(float c[4], const uint32_t a[4], const uint32_t b[2]) {
    asm volatile(
        "mma.sync.aligned.m16n8k8.row.col.f32.tf32.tf32.f32 "
        "{%0,%1,%2,%3}, {%4,%5,%6,%7}, {%8,%9}, {%0,%1,%2,%3};"
        : "+f"(c[0]), "+f"(c[1]), "+f"(c[2]), "+f"(c[3])
        : "r"(a[0]), "r"(a[1]), "r"(a[2]), "r"(a[3]), "r"(b[0]), "r"(b[1]));
}

__global__ void spconv_zero_kernel(float4* __restrict__ out, int n4) {
    int i = blockIdx.x * blockDim.x + threadIdx.x;
    if (i < n4) out[i] = make_float4(0.f, 0.f, 0.f, 0.f);
}

__global__ __launch_bounds__(NTHREADS, 2)
void spconv_mma_kernel(const float* __restrict__ feats,
                       const float* __restrict__ kern,
                       const int*   __restrict__ in_map,
                       const int*   __restrict__ out_map,
                       float*       __restrict__ out)
{
    extern __shared__ uint32_t sh[];
    uint32_t* Ash   = sh;                       // [TILE_M][FSTRIDE] tf32
    uint32_t* Bpack = sh + TILE_M * FSTRIDE;    // fragment-packed W^T (4096 words)

    const int k   = blockIdx.y;
    const int m0  = blockIdx.x * TILE_M;
    const int tid = threadIdx.x;
    const int wid = tid >> 5;
    const int lid = tid & 31;

    // ---- Gather A: 256 rows x 64 cols, tf32-rounded, STS.128 ----
    {
        const int rlane = tid & 15;            // 16B chunk of the row
        const int rgrp  = tid >> 4;            // 32 rows per sweep
        const int* im = in_map + (size_t)k * MPAIRS;
        #pragma unroll
        for (int r = rgrp; r < TILE_M; r += 32) {
            int m = m0 + r;
            uint4 u = make_uint4(0u, 0u, 0u, 0u);
            if (m < MPAIRS) {
                int row = im[m];
                float4 v = *reinterpret_cast<const float4*>(feats + (size_t)row * CIN + rlane * 4);
                u.x = f2tf32(v.x); u.y = f2tf32(v.y); u.z = f2tf32(v.z); u.w = f2tf32(v.w);
            }
            *reinterpret_cast<uint4*>(Ash + r * FSTRIDE + rlane * 4) = u;
        }
    }

    // ---- Stage B = W[k]^T, fragment-packed, cout rows permuted ----
    // cout perm: P=o>>4, local=o&15, tt=local>>2, rr=local&3:
    //   pos = (2P + (rr>>1))*8 + 2*tt + (rr&1); nt=pos>>3, g=pos&7.
    // fragment packing: cin i -> (s=i>>3, j=i&7, t=j&3, e=j>>2);
    //   Bpack[((nt*8+s)*32 + g*4 + t)*2 + e] => lane reads its b-pair as LDS.64.
    {
        const float* W = kern + (size_t)k * CIN * COUT;
        #pragma unroll
        for (int idx = tid; idx < CIN * COUT; idx += NTHREADS) {
            int i = idx >> 6;                  // cin
            int o = idx & 63;                  // cout (contiguous -> coalesced LDG)
            int P = o >> 4, local = o & 15;
            int tt = local >> 2, rr = local & 3;
            int pos = (2 * P + (rr >> 1)) * 8 + 2 * tt + (rr & 1);
            int nt = pos >> 3, g = pos & 7;
            int s = i >> 3, j = i & 7;
            int t = j & 3, e = j >> 2;
            Bpack[(((nt * 8 + s) * 32) + g * 4 + t) * 2 + e] = f2tf32(W[idx]);
        }
    }
    __syncthreads();

    // ---- Warp GEMM: warp (rgrpw, chalf) -> rows [32*rgrpw,+32), couts half ----
    const int g     = lid >> 2;                // row-group within mma tile
    const int t     = lid & 3;                 // thread in group
    const int rgrpw = wid >> 1;                // 0..7
    const int chalf = wid & 1;                 // 0..1
    const int mbase = rgrpw * 32;

    float acc[2][4][4];
    #pragma unroll
    for (int mt = 0; mt < 2; ++mt)
        #pragma unroll
        for (int nt = 0; nt < 4; ++nt)
            #pragma unroll
            for (int e = 0; e < 4; ++e) acc[mt][nt][e] = 0.f;

    #pragma unroll
    for (int s = 0; s < 8; ++s) {
        const int kc = s * 8;
        uint32_t af[2][4];
        #pragma unroll
        for (int mt = 0; mt < 2; ++mt) {
            const uint32_t* ap = Ash + (mbase + mt * 16 + g) * FSTRIDE + kc + t;
            af[mt][0] = ap[0];
            af[mt][1] = ap[8 * FSTRIDE];
            af[mt][2] = ap[4];
            af[mt][3] = ap[8 * FSTRIDE + 4];
        }
        #pragma unroll
        for (int nt = 0; nt < 4; ++nt) {
            const int nb = chalf * 4 + nt;
            uint32_t bf[2];
            const uint32_t* bp = Bpack + ((nb * 8 + s) * 32 + lid) * 2;
            asm volatile("ld.shared.v2.b32 {%0, %1}, [%2];"
                         : "=r"(bf[0]), "=r"(bf[1])
                         : "r"((uint32_t)(__cvta_generic_to_shared(bp))));
            mma_tf32(acc[0][nt], af[0], bf);
            mma_tf32(acc[1][nt], af[1], bf);
        }
    }

    // ---- Scatter: vectorized global reductions, 4 contiguous couts per red ----
    // acc tile T = chalf*4 + nt; tiles (2pp, 2pp+1) within half -> P = 2*chalf+pp,
    // couts 16P + 4t .. +3.
    {
        const int* om = out_map + (size_t)k * MPAIRS;
        #pragma unroll
        for (int mt = 0; mt < 2; ++mt) {
            #pragma unroll
            for (int half = 0; half < 2; ++half) {   // rows g and g+8
                int m = m0 + mbase + mt * 16 + g + half * 8;
                if (m < MPAIRS) {
                    int orow = om[m];
                    float* dst = out + (size_t)orow * COUT + t * 4;
                    #pragma unroll
                    for (int pp = 0; pp < 2; ++pp) {
                        int P = chalf * 2 + pp;
                        asm volatile("red.global.add.v4.f32 [%0], {%1,%2,%3,%4};"
                                     :: "l"(dst + 16 * P),
                                        "f"(acc[mt][2 * pp][half * 2]),
                                        "f"(acc[mt][2 * pp][half * 2 + 1]),
                                        "f"(acc[mt][2 * pp + 1][half * 2]),
                                        "f"(acc[mt][2 * pp + 1][half * 2 + 1]) : "memory");
                    }
                }
            }
        }
    }
}

extern "C" void kernel_launch(void* const* d_in, const int* in_sizes, int n_in,
                              void* d_out, int out_size) {
    const float* feats   = (const float*)d_in[0];   // [N, 64]
    const float* kern    = (const float*)d_in[1];   // [27, 64, 64]
    const int*   in_map  = (const int*)d_in[2];     // [27, 50000]
    const int*   out_map = (const int*)d_in[3];     // [27, 50000]
    float* out = (float*)d_out;                     // [N, 64]

    int n4 = NVOX * COUT / 4;
    spconv_zero_kernel<<<(n4 + 255) / 256, 256>>>((float4*)out, n4);

    int smem_bytes = SMEM_WORDS * (int)sizeof(uint32_t);   // 85.8 KB -> 2 CTAs/SM
    cudaFuncSetAttribute(spconv_mma_kernel,
                         cudaFuncAttributeMaxDynamicSharedMemorySize, smem_bytes);
    dim3 grid((MPAIRS + TILE_M - 1) / TILE_M, KOFF);
    spconv_mma_kernel<<<grid, NTHREADS, smem_bytes>>>(feats, kern, in_map, out_map, out);
}

// round 7
// speedup vs baseline: 1.6663x; 1.0356x over previous
#include <cuda_runtime.h>
#include <cstdint>

// Sparse 3D conv, persistent-CTA pipelined version (mma.sync tf32; tcgen05 PTX
// rejected by harness's compute_103 target).
// out[out_map[k,m]] += feats[in_map[k,m]] @ kernel[k]
// N=200000, K=27, M=50000, Cin=Cout=64, fp32 in/out, tf32(RNA at LDS) MMA.

#define KOFF    27
#define MPAIRS  50000
#define NVOX    200000
#define CIN     64
#define COUT    64
#define TILE_M  256
#define NTHREADS 512
#define TPK     196                 // tiles per kernel offset (ceil(50000/256))
#define NTILES  (KOFF * TPK)        // 5292
#define NCTA    304                 // 2 per SM on 152-SM GB300
#define QT      17                  // 5292 = 304*17 + 124
#define RT      124
#define ASTRIDE 36                  // words per row in half-buffer (32 + 4 pad)

#define ABUF_WORDS (TILE_M * ASTRIDE)          // 9216 words per buffer
#define OFF_B      (2 * ABUF_WORDS)            // 18432: fragment-packed W^T (4096 w)
#define OFF_IDX    (OFF_B + CIN * COUT)        // 22528: IDX[3][256]
#define OFF_OMAP   (OFF_IDX + 3 * TILE_M)      // 23296: OMAP[3][256]
#define SMEM_WORDS (OFF_OMAP + 3 * TILE_M)     // 24064 words = 96256 B

__device__ __forceinline__ uint32_t f2tf32(float f) {
    uint32_t r;
    asm("cvt.rna.tf32.f32 %0, %1;" : "=r"(r) : "f"(f));
    return r;
}
__device__ __forceinline__ void cp16(uint32_t dst, const void* src) {
    asm volatile("cp.async.cg.shared.global [%0], [%1], 16;" :: "r"(dst), "l"(src));
}
__device__ __forceinline__ void mma_tf32(float c[4], const uint32_t a[4], const uint32_t b[2]) {
    asm volatile(
        "mma.sync.aligned.m16n8k8.row.col.f32.tf32.tf32.f32 "
        "{%0,%1,%2,%3}, {%4,%5,%6,%7}, {%8,%9}, {%0,%1,%2,%3};"
        : "+f"(c[0]), "+f"(c[1]), "+f"(c[2]), "+f"(c[3])
        : "r"(a[0]), "r"(a[1]), "r"(a[2]), "r"(a[3]), "r"(b[0]), "r"(b[1]));
}

__global__ void spconv_zero_kernel(float4* __restrict__ out, int n4) {
    int i = blockIdx.x * blockDim.x + threadIdx.x;
    if (i < n4) out[i] = make_float4(0.f, 0.f, 0.f, 0.f);
}

__global__ __launch_bounds__(NTHREADS, 2)
void spconv_pers_kernel(const float* __restrict__ feats,
                        const float* __restrict__ kern,
                        const int*   __restrict__ in_map,
                        const int*   __restrict__ out_map,
                        float*       __restrict__ out)
{
    extern __shared__ uint32_t sh[];
    const uint32_t shb = (uint32_t)__cvta_generic_to_shared(sh);

    const int tid = threadIdx.x;
    const int wid = tid >> 5;
    const int lid = tid & 31;
    const int cta = blockIdx.x;

    const int t0  = cta * QT + (cta < RT ? cta : RT);
    const int cnt = QT + (cta < RT ? 1 : 0);
    const int S   = cnt * 2;

    const int g = lid >> 2, t = lid & 3;
    const int rgrpw = wid >> 1, chalf = wid & 1;
    const int mbase = rgrpw * 32;

    // ---- Prologue: fetch idx/omap for tile t0 into slot 0 ----
    {
        int tt = t0;
        int k0 = tt / TPK, m00 = (tt % TPK) * TILE_M;
        if (tid < 64) {
            int m = m00 + tid * 4;
            if (m < MPAIRS)
                cp16(shb + (OFF_IDX + tid * 4) * 4, in_map + (size_t)k0 * MPAIRS + m);
        } else if (tid < 128) {
            int ci = tid - 64, m = m00 + ci * 4;
            if (m < MPAIRS)
                cp16(shb + (OFF_OMAP + ci * 4) * 4, out_map + (size_t)k0 * MPAIRS + m);
        }
        asm volatile("cp.async.commit_group;" ::: "memory");
        asm volatile("cp.async.wait_group 0;" ::: "memory");
        __syncthreads();
    }

    // Stage issuer: gathers A half-tile for stage sp; if sp is a first-half,
    // also prefetches idx/omap for the NEXT tile (slot (li+1)%3).
    auto issue_stage = [&](int sp) {
        int li = sp >> 1, h = sp & 1;
        int tt = t0 + li;
        int m0 = (tt % TPK) * TILE_M;
        int slot = li % 3;
        uint32_t abase = shb + ((sp & 1) * ABUF_WORDS) * 4;
        #pragma unroll
        for (int j = 0; j < 4; ++j) {
            int cch = tid + j * NTHREADS;
            int row = cch >> 3, ch = cch & 7;
            int m = m0 + row;
            int gi = (int)sh[OFF_IDX + slot * TILE_M + row];
            int srow = (m < MPAIRS) ? gi : 0;
            cp16(abase + (row * ASTRIDE + ch * 4) * 4,
                 feats + (size_t)srow * CIN + h * 32 + ch * 4);
        }
        if (h == 0 && li + 1 < cnt) {
            int tt2 = tt + 1;
            int k2 = tt2 / TPK, m02 = (tt2 % TPK) * TILE_M;
            int slot2 = (li + 1) % 3;
            if (tid < 64) {
                int m = m02 + tid * 4;
                if (m < MPAIRS)
                    cp16(shb + (OFF_IDX + slot2 * TILE_M + tid * 4) * 4,
                         in_map + (size_t)k2 * MPAIRS + m);
            } else if (tid < 128) {
                int ci = tid - 64, m = m02 + ci * 4;
                if (m < MPAIRS)
                    cp16(shb + (OFF_OMAP + slot2 * TILE_M + ci * 4) * 4,
                         out_map + (size_t)k2 * MPAIRS + m);
            }
        }
        asm volatile("cp.async.commit_group;" ::: "memory");
    };

    issue_stage(0);

    float acc[2][4][4];
    int cur_k = -1;

    for (int s = 0; s < S; ++s) {
        if (s + 1 < S) {
            issue_stage(s + 1);
            asm volatile("cp.async.wait_group 1;" ::: "memory");
        } else {
            asm volatile("cp.async.wait_group 0;" ::: "memory");
        }
        __syncthreads();

        const int li = s >> 1, h = s & 1;
        const int tt = t0 + li;
        const int kk = tt / TPK;
        const int m0 = (tt % TPK) * TILE_M;

        if (h == 0) {
            if (kk != cur_k) {
                // ---- Stage B = W[kk]^T, fragment-packed, cout rows permuted ----
                const float* W = kern + (size_t)kk * CIN * COUT;
                #pragma unroll
                for (int idx = tid; idx < CIN * COUT; idx += NTHREADS) {
                    int i = idx >> 6;              // cin
                    int o = idx & 63;              // cout
                    int P = o >> 4, local = o & 15;
                    int ttq = local >> 2, rr = local & 3;
                    int pos = (2 * P + (rr >> 1)) * 8 + 2 * ttq + (rr & 1);
                    int nt = pos >> 3, gg = pos & 7;
                    int si = i >> 3, j = i & 7;
                    int tj = j & 3, e = j >> 2;
                    sh[OFF_B + (((nt * 8 + si) * 32) + gg * 4 + tj) * 2 + e] = f2tf32(W[idx]);
                }
                cur_k = kk;
                __syncthreads();
            }
            #pragma unroll
            for (int mt = 0; mt < 2; ++mt)
                #pragma unroll
                for (int nt = 0; nt < 4; ++nt)
                    #pragma unroll
                    for (int e = 0; e < 4; ++e) acc[mt][nt][e] = 0.f;
        }

        // ---- GEMM: 4 k-steps over this half-buffer (raw fp32 -> RNA tf32) ----
        const uint32_t* Abuf = sh + (s & 1) * ABUF_WORDS;
        #pragma unroll
        for (int sl = 0; sl < 4; ++sl) {
            const int sg = h * 4 + sl;
            uint32_t af[2][4];
            #pragma unroll
            for (int mt = 0; mt < 2; ++mt) {
                const uint32_t* ap = Abuf + (mbase + mt * 16 + g) * ASTRIDE + sl * 8 + t;
                af[mt][0] = f2tf32(__uint_as_float(ap[0]));
                af[mt][1] = f2tf32(__uint_as_float(ap[8 * ASTRIDE]));
                af[mt][2] = f2tf32(__uint_as_float(ap[4]));
                af[mt][3] = f2tf32(__uint_as_float(ap[8 * ASTRIDE + 4]));
            }
            #pragma unroll
            for (int nt = 0; nt < 4; ++nt) {
                const int nb = chalf * 4 + nt;
                uint32_t bf[2];
                uint32_t baddr = shb + (OFF_B + ((nb * 8 + sg) * 32 + lid) * 2) * 4;
                asm volatile("ld.shared.v2.b32 {%0, %1}, [%2];"
                             : "=r"(bf[0]), "=r"(bf[1]) : "r"(baddr));
                mma_tf32(acc[0][nt], af[0], bf);
                mma_tf32(acc[1][nt], af[1], bf);
            }
        }

        if (h == 1) {
            // ---- Scatter: v4 global reductions, 4 contiguous couts each ----
            const int slot = li % 3;
            #pragma unroll
            for (int mt = 0; mt < 2; ++mt) {
                #pragma unroll
                for (int half = 0; half < 2; ++half) {
                    int ml = mbase + mt * 16 + g + half * 8;
                    int m = m0 + ml;
                    if (m < MPAIRS) {
                        int orow = (int)sh[OFF_OMAP + slot * TILE_M + ml];
                        float* dst = out + (size_t)orow * COUT + t * 4;
                        #pragma unroll
                        for (int pp = 0; pp < 2; ++pp) {
                            int P = chalf * 2 + pp;
                            asm volatile("red.global.add.v4.f32 [%0], {%1,%2,%3,%4};"
                                         :: "l"(dst + 16 * P),
                                            "f"(acc[mt][2 * pp][half * 2]),
                                            "f"(acc[mt][2 * pp][half * 2 + 1]),
                                            "f"(acc[mt][2 * pp + 1][half * 2]),
                                            "f"(acc[mt][2 * pp + 1][half * 2 + 1]) : "memory");
                        }
                    }
                }
            }
        }
        __syncthreads();   // A-buf (s&1) free for reuse at iter s+1's issue
    }
}

extern "C" void kernel_launch(void* const* d_in, const int* in_sizes, int n_in,
                              void* d_out, int out_size) {
    const float* feats   = (const float*)d_in[0];   // [N, 64]
    const float* kern    = (const float*)d_in[1];   // [27, 64, 64]
    const int*   in_map  = (const int*)d_in[2];     // [27, 50000]
    const int*   out_map = (const int*)d_in[3];     // [27, 50000]
    float* out = (float*)d_out;                     // [N, 64]

    int n4 = NVOX * COUT / 4;
    spconv_zero_kernel<<<(n4 + 255) / 256, 256>>>((float4*)out, n4);

    int smem_bytes = SMEM_WORDS * (int)sizeof(uint32_t);   // 96256 B -> 2 CTAs/SM
    cudaFuncSetAttribute(spconv_pers_kernel,
                         cudaFuncAttributeMaxDynamicSharedMemorySize, smem_bytes);
    spconv_pers_kernel<<<NCTA, NTHREADS, smem_bytes>>>(feats, kern, in_map, out_map, out);
}

// round 9
// speedup vs baseline: 1.8980x; 1.1390x over previous
#include <cuda_runtime.h>
#include <cstdint>

// Sparse 3D conv, persistent-CTA pipelined (mma.sync tf32; tcgen05 PTX rejected
// by harness's compute_103 target).
// out[out_map[k,m]] += feats[in_map[k,m]] @ kernel[k]
// N=200000, K=27, M=50000, Cin=Cout=64, fp32 in/out, tf32(RNA at LDS) MMA.
//
// R8: 256-thread CTAs, TILE_M=128, 4 CTAs/SM (4 independent pipelines),
// single barrier per pipeline stage.

#define KOFF    27
#define MPAIRS  50000
#define NVOX    200000
#define CIN     64
#define COUT    64
#define TILE_M  128
#define NTHREADS 256
#define TPK     391                 // ceil(50000/128)
#define NTILES  (KOFF * TPK)        // 10557
#define NCTA    608                 // 4 per SM on 152-SM GB300
#define QT      17                  // 10557 = 608*17 + 221
#define RT      221
#define ASTRIDE 36                  // words per row in half-buffer (32 + 4 pad)

#define ABUF_WORDS (TILE_M * ASTRIDE)          // 4608 words per buffer
#define OFF_B      (2 * ABUF_WORDS)            // 9216: fragment-packed W^T (4096 w)
#define OFF_IDX    (OFF_B + CIN * COUT)        // 13312: IDX[3][128]
#define OFF_OMAP   (OFF_IDX + 3 * TILE_M)      // 13696: OMAP[3][128]
#define SMEM_WORDS (OFF_OMAP + 3 * TILE_M)     // 14080 words = 56320 B

__device__ __forceinline__ uint32_t f2tf32(float f) {
    uint32_t r;
    asm("cvt.rna.tf32.f32 %0, %1;" : "=r"(r) : "f"(f));
    return r;
}
__device__ __forceinline__ void cp16(uint32_t dst, const void* src) {
    asm volatile("cp.async.cg.shared.global [%0], [%1], 16;" :: "r"(dst), "l"(src));
}
__device__ __forceinline__ void mma_tf32(float c[4], const uint32_t a[4], const uint32_t b[2]) {
    asm volatile(
        "mma.sync.aligned.m16n8k8.row.col.f32.tf32.tf32.f32 "
        "{%0,%1,%2,%3}, {%4,%5,%6,%7}, {%8,%9}, {%0,%1,%2,%3};"
        : "+f"(c[0]), "+f"(c[1]), "+f"(c[2]), "+f"(c[3])
        : "r"(a[0]), "r"(a[1]), "r"(a[2]), "r"(a[3]), "r"(b[0]), "r"(b[1]));
}

__global__ void spconv_zero_kernel(float4* __restrict__ out, int n4) {
    int i = blockIdx.x * blockDim.x + threadIdx.x;
    if (i < n4) out[i] = make_float4(0.f, 0.f, 0.f, 0.f);
}

__global__ __launch_bounds__(NTHREADS, 4)
void spconv_pers_kernel(const float* __restrict__ feats,
                        const float* __restrict__ kern,
                        const int*   __restrict__ in_map,
                        const int*   __restrict__ out_map,
                        float*       __restrict__ out)
{
    extern __shared__ uint32_t sh[];
    const uint32_t shb = (uint32_t)__cvta_generic_to_shared(sh);

    const int tid = threadIdx.x;
    const int wid = tid >> 5;
    const int lid = tid & 31;
    const int cta = blockIdx.x;

    const int t0  = cta * QT + (cta < RT ? cta : RT);
    const int cnt = QT + (cta < RT ? 1 : 0);
    const int S   = cnt * 2;

    const int g = lid >> 2, t = lid & 3;
    const int rgrpw = wid >> 1, chalf = wid & 1;
    const int mbase = rgrpw * 32;

    // ---- Prologue: fetch idx/omap for tile t0 into slot 0 ----
    {
        int tt = t0;
        int k0 = tt / TPK, m00 = (tt % TPK) * TILE_M;
        if (tid < 32) {
            int m = m00 + tid * 4;
            if (m < MPAIRS)
                cp16(shb + (OFF_IDX + tid * 4) * 4, in_map + (size_t)k0 * MPAIRS + m);
        } else if (tid < 64) {
            int ci = tid - 32, m = m00 + ci * 4;
            if (m < MPAIRS)
                cp16(shb + (OFF_OMAP + ci * 4) * 4, out_map + (size_t)k0 * MPAIRS + m);
        }
        asm volatile("cp.async.commit_group;" ::: "memory");
        asm volatile("cp.async.wait_group 0;" ::: "memory");
        __syncthreads();
    }

    // Gathers A half-tile for stage sp; first-half stages also prefetch
    // idx/omap for the NEXT tile into ring slot (li+1)%3.
    auto issue_stage = [&](int sp) {
        int li = sp >> 1, h = sp & 1;
        int tt = t0 + li;
        int m0 = (tt % TPK) * TILE_M;
        int slot = li % 3;
        uint32_t abase = shb + ((sp & 1) * ABUF_WORDS) * 4;
        #pragma unroll
        for (int j = 0; j < 4; ++j) {
            int cch = tid + j * NTHREADS;
            int row = cch >> 3, ch = cch & 7;
            int m = m0 + row;
            int gi = (int)sh[OFF_IDX + slot * TILE_M + row];
            int srow = (m < MPAIRS) ? gi : 0;
            cp16(abase + (row * ASTRIDE + ch * 4) * 4,
                 feats + (size_t)srow * CIN + h * 32 + ch * 4);
        }
        if (h == 0 && li + 1 < cnt) {
            int tt2 = tt + 1;
            int k2 = tt2 / TPK, m02 = (tt2 % TPK) * TILE_M;
            int slot2 = (li + 1) % 3;
            if (tid < 32) {
                int m = m02 + tid * 4;
                if (m < MPAIRS)
                    cp16(shb + (OFF_IDX + slot2 * TILE_M + tid * 4) * 4,
                         in_map + (size_t)k2 * MPAIRS + m);
            } else if (tid < 64) {
                int ci = tid - 32, m = m02 + ci * 4;
                if (m < MPAIRS)
                    cp16(shb + (OFF_OMAP + slot2 * TILE_M + ci * 4) * 4,
                         out_map + (size_t)k2 * MPAIRS + m);
            }
        }
        asm volatile("cp.async.commit_group;" ::: "memory");
    };

    issue_stage(0);

    float acc[2][4][4];
    int cur_k = -1;

    for (int s = 0; s < S; ++s) {
        // Only group s is in flight here; wait-all completes it, the barrier
        // publishes it CTA-wide AND frees buffer (s+1)%2 (compute(s-1) done).
        asm volatile("cp.async.wait_group 0;" ::: "memory");
        __syncthreads();

        if (s + 1 < S) issue_stage(s + 1);

        const int li = s >> 1, h = s & 1;
        const int tt = t0 + li;
        const int kk = tt / TPK;
        const int m0 = (tt % TPK) * TILE_M;

        if (h == 0) {
            if (kk != cur_k) {
                // ---- Stage B = W[kk]^T, fragment-packed, cout rows permuted ----
                const float* W = kern + (size_t)kk * CIN * COUT;
                #pragma unroll
                for (int idx = tid; idx < CIN * COUT; idx += NTHREADS) {
                    int i = idx >> 6;              // cin
                    int o = idx & 63;              // cout
                    int P = o >> 4, local = o & 15;
                    int ttq = local >> 2, rr = local & 3;
                    int pos = (2 * P + (rr >> 1)) * 8 + 2 * ttq + (rr & 1);
                    int nt = pos >> 3, gg = pos & 7;
                    int si = i >> 3, j = i & 7;
                    int tj = j & 3, e = j >> 2;
                    sh[OFF_B + (((nt * 8 + si) * 32) + gg * 4 + tj) * 2 + e] = f2tf32(W[idx]);
                }
                cur_k = kk;
                __syncthreads();
            }
            #pragma unroll
            for (int mt = 0; mt < 2; ++mt)
                #pragma unroll
                for (int nt = 0; nt < 4; ++nt)
                    #pragma unroll
                    for (int e = 0; e < 4; ++e) acc[mt][nt][e] = 0.f;
        }

        // ---- GEMM: 4 k-steps over this half-buffer (raw fp32 -> RNA tf32) ----
        const uint32_t* Abuf = sh + (s & 1) * ABUF_WORDS;
        #pragma unroll
        for (int sl = 0; sl < 4; ++sl) {
            const int sg = h * 4 + sl;
            uint32_t af[2][4];
            #pragma unroll
            for (int mt = 0; mt < 2; ++mt) {
                const uint32_t* ap = Abuf + (mbase + mt * 16 + g) * ASTRIDE + sl * 8 + t;
                af[mt][0] = f2tf32(__uint_as_float(ap[0]));
                af[mt][1] = f2tf32(__uint_as_float(ap[8 * ASTRIDE]));
                af[mt][2] = f2tf32(__uint_as_float(ap[4]));
                af[mt][3] = f2tf32(__uint_as_float(ap[8 * ASTRIDE + 4]));
            }
            #pragma unroll
            for (int nt = 0; nt < 4; ++nt) {
                const int nb = chalf * 4 + nt;
                uint32_t bf[2];
                uint32_t baddr = shb + (OFF_B + ((nb * 8 + sg) * 32 + lid) * 2) * 4;
                asm volatile("ld.shared.v2.b32 {%0, %1}, [%2];"
                             : "=r"(bf[0]), "=r"(bf[1]) : "r"(baddr));
                mma_tf32(acc[0][nt], af[0], bf);
                mma_tf32(acc[1][nt], af[1], bf);
            }
        }

        if (h == 1) {
            // ---- Scatter: v4 global reductions, 4 contiguous couts each ----
            const int slot = li % 3;
            #pragma unroll
            for (int mt = 0; mt < 2; ++mt) {
                #pragma unroll
                for (int half = 0; half < 2; ++half) {
                    int ml = mbase + mt * 16 + g + half * 8;
                    int m = m0 + ml;
                    if (m < MPAIRS) {
                        int orow = (int)sh[OFF_OMAP + slot * TILE_M + ml];
                        float* dst = out + (size_t)orow * COUT + t * 4;
                        #pragma unroll
                        for (int pp = 0; pp < 2; ++pp) {
                            int P = chalf * 2 + pp;
                            asm volatile("red.global.add.v4.f32 [%0], {%1,%2,%3,%4};"
                                         :: "l"(dst + 16 * P),
                                            "f"(acc[mt][2 * pp][half * 2]),
                                            "f"(acc[mt][2 * pp][half * 2 + 1]),
                                            "f"(acc[mt][2 * pp + 1][half * 2]),
                                            "f"(acc[mt][2 * pp + 1][half * 2 + 1]) : "memory");
                        }
                    }
                }
            }
        }
    }
}

extern "C" void kernel_launch(void* const* d_in, const int* in_sizes, int n_in,
                              void* d_out, int out_size) {
    const float* feats   = (const float*)d_in[0];   // [N, 64]
    const float* kern    = (const float*)d_in[1];   // [27, 64, 64]
    const int*   in_map  = (const int*)d_in[2];     // [27, 50000]
    const int*   out_map = (const int*)d_in[3];     // [27, 50000]
    float* out = (float*)d_out;                     // [N, 64]

    int n4 = NVOX * COUT / 4;
    spconv_zero_kernel<<<(n4 + 255) / 256, 256>>>((float4*)out, n4);

    int smem_bytes = SMEM_WORDS * (int)sizeof(uint32_t);   // 56320 B -> 4 CTAs/SM
    cudaFuncSetAttribute(spconv_pers_kernel,
                         cudaFuncAttributeMaxDynamicSharedMemorySize, smem_bytes);
    spconv_pers_kernel<<<NCTA, NTHREADS, smem_bytes>>>(feats, kern, in_map, out_map, out);
}